// round 15
// baseline (speedup 1.0000x reference)
#include <cuda_runtime.h>
#include <cuda_fp16.h>
#include <cuda_bf16.h>
#include <cstdint>

#define N_NODES 50000
#define N_EDGES 800000
#define D 64

// Scratch (no allocations allowed): static device globals.
__device__ __align__(16) float  g_agg[N_NODES * D];   // scatter-sum of edge_attr
__device__ __align__(16) float  g_cnt[N_NODES];       // per-src edge counts
__device__ __align__(16) __half g_nemb[N_NODES * D];  // fp16 node embeddings (row = 128B)
__device__ int g_is64;                                // 1 = edge_index is int64

__device__ __forceinline__ int load_index(const void* ei, int pos, int is64) {
    if (is64) return (int)((const long long*)ei)[pos];
    return ((const int*)ei)[pos];
}

// ---------------------------------------------------------------------------
// k_detect: int64 vs int32 edge_index (int64 indices < 50000 -> hi words 0).
// ---------------------------------------------------------------------------
__global__ void k_detect(const int2* __restrict__ ei) {
    __shared__ int any_hi;
    if (threadIdx.x == 0) any_hi = 0;
    __syncthreads();
    int local = 0;
    for (int i = threadIdx.x; i < 4096; i += blockDim.x)
        local |= ei[i].y;
    local |= __shfl_xor_sync(0xffffffffu, local, 16);
    local |= __shfl_xor_sync(0xffffffffu, local, 8);
    local |= __shfl_xor_sync(0xffffffffu, local, 4);
    local |= __shfl_xor_sync(0xffffffffu, local, 2);
    local |= __shfl_xor_sync(0xffffffffu, local, 1);
    if ((threadIdx.x & 31) == 0 && local) any_hi = 1;
    __syncthreads();
    if (threadIdx.x == 0) g_is64 = (any_hi == 0) ? 1 : 0;
}

// ---------------------------------------------------------------------------
// k1: scatter-add edge_attr rows onto g_agg[src] with vector RED (v4.f32).
// 16 lanes per edge (dense row reads), TWO edges per thread (e, e+400000).
// edge_attr read once -> __ldcs streaming keeps g_agg L2-resident.
// ---------------------------------------------------------------------------
__global__ void k_scatter(const float* __restrict__ edge_attr,
                          const void* __restrict__ edge_index) {
    const int HALF = N_EDGES / 2;   // 400000
    int t = blockIdx.x * blockDim.x + threadIdx.x;
    if (t >= HALF * 16) return;
    int is64 = g_is64;
    int e0 = t >> 4;
    int c  = t & 15;
    int e1 = e0 + HALF;

    int s0 = load_index(edge_index, e0, is64);
    int s1 = load_index(edge_index, e1, is64);

    float4 v0 = __ldcs(reinterpret_cast<const float4*>(edge_attr) + (size_t)e0 * 16 + c);
    float4 v1 = __ldcs(reinterpret_cast<const float4*>(edge_attr) + (size_t)e1 * 16 + c);

    if ((unsigned)s0 < N_NODES) {
        float* p = &g_agg[s0 * D + c * 4];
        asm volatile("red.global.add.v4.f32 [%0], {%1,%2,%3,%4};"
                     :: "l"(p), "f"(v0.x), "f"(v0.y), "f"(v0.z), "f"(v0.w) : "memory");
        if (c == 0) atomicAdd(&g_cnt[s0], 1.0f);
    }
    if ((unsigned)s1 < N_NODES) {
        float* p = &g_agg[s1 * D + c * 4];
        asm volatile("red.global.add.v4.f32 [%0], {%1,%2,%3,%4};"
                     :: "l"(p), "f"(v1.x), "f"(v1.y), "f"(v1.z), "f"(v1.w) : "memory");
        if (c == 0) atomicAdd(&g_cnt[s1], 1.0f);
    }
}

// ---------------------------------------------------------------------------
// k2: nemb = sigmoid((node_attr + agg*0.5/max(cnt,1)) @ W^T + b), stored fp16.
// Register-tiled GEMM, 4x4 tile/thread, float4 LDS operand reads, stride 68.
// ---------------------------------------------------------------------------
#define S 68
__global__ void __launch_bounds__(256) k_node(const float* __restrict__ node_attr,
                                              const float* __restrict__ W,
                                              const float* __restrict__ b) {
    __shared__ float wt[64 * S];    // wt[k*S + j] = W[j*64 + k]
    __shared__ float xst[64 * S];   // xst[k*S + n] = x[node nb+n][k]
    __shared__ float bs[64];
    __shared__ float sinv[64];      // 0.5 / max(cnt, 1) per node

    const int tid = threadIdx.x;
    const int nb  = blockIdx.x * 64;

    if (tid < 64) {
        bs[tid] = b[tid];
        int n_g = nb + tid;
        float cnt = (n_g < N_NODES) ? g_cnt[n_g] : 1.0f;
        sinv[tid] = 0.5f / fmaxf(cnt, 1.0f);
    }
    #pragma unroll
    for (int i = tid; i < 64 * 64; i += 256) {
        int j = i >> 6;
        int k = i & 63;
        wt[k * S + j] = W[i];
    }
    __syncthreads();

    #pragma unroll
    for (int i = tid; i < 64 * 64; i += 256) {
        int n = i >> 6;
        int k = i & 63;
        int n_g = nb + n;
        float v = 0.0f;
        if (n_g < N_NODES) {
            v = node_attr[n_g * D + k] + g_agg[n_g * D + k] * sinv[n];
        }
        xst[k * S + n] = v;
    }
    __syncthreads();

    const int jg = tid & 15;
    const int ng = tid >> 4;
    const int j0 = jg * 4;
    const int n0 = ng * 4;

    float acc[4][4];
    #pragma unroll
    for (int a = 0; a < 4; a++)
        #pragma unroll
        for (int c = 0; c < 4; c++)
            acc[a][c] = bs[j0 + c];

    #pragma unroll 8
    for (int k = 0; k < 64; k++) {
        float4 xv = *reinterpret_cast<const float4*>(&xst[k * S + n0]);
        float4 wv = *reinterpret_cast<const float4*>(&wt[k * S + j0]);
        acc[0][0] = fmaf(xv.x, wv.x, acc[0][0]); acc[0][1] = fmaf(xv.x, wv.y, acc[0][1]);
        acc[0][2] = fmaf(xv.x, wv.z, acc[0][2]); acc[0][3] = fmaf(xv.x, wv.w, acc[0][3]);
        acc[1][0] = fmaf(xv.y, wv.x, acc[1][0]); acc[1][1] = fmaf(xv.y, wv.y, acc[1][1]);
        acc[1][2] = fmaf(xv.y, wv.z, acc[1][2]); acc[1][3] = fmaf(xv.y, wv.w, acc[1][3]);
        acc[2][0] = fmaf(xv.z, wv.x, acc[2][0]); acc[2][1] = fmaf(xv.z, wv.y, acc[2][1]);
        acc[2][2] = fmaf(xv.z, wv.z, acc[2][2]); acc[2][3] = fmaf(xv.z, wv.w, acc[2][3]);
        acc[3][0] = fmaf(xv.w, wv.x, acc[3][0]); acc[3][1] = fmaf(xv.w, wv.y, acc[3][1]);
        acc[3][2] = fmaf(xv.w, wv.z, acc[3][2]); acc[3][3] = fmaf(xv.w, wv.w, acc[3][3]);
    }

    #pragma unroll
    for (int a = 0; a < 4; a++) {
        int n_g = nb + n0 + a;
        if (n_g < N_NODES) {
            float s0 = 1.0f / (1.0f + __expf(-acc[a][0]));
            float s1 = 1.0f / (1.0f + __expf(-acc[a][1]));
            float s2 = 1.0f / (1.0f + __expf(-acc[a][2]));
            float s3 = 1.0f / (1.0f + __expf(-acc[a][3]));
            __half2 h0 = __floats2half2_rn(s0, s1);
            __half2 h1 = __floats2half2_rn(s2, s3);
            uint2 pk;
            pk.x = *reinterpret_cast<unsigned int*>(&h0);
            pk.y = *reinterpret_cast<unsigned int*>(&h1);
            *reinterpret_cast<uint2*>(&g_nemb[n_g * D + j0]) = pk;
        }
    }
}
#undef S

// ---------------------------------------------------------------------------
// k3: edge output via TMA bulk store.
// Block = 256 threads handles 128 contiguous edges (32KB). Each thread: 4
// edges (8 gathers in flight, dense 8-lanes-per-row layout), results to smem
// (STS, no LSU STG.128 issue cost, no L1tex store wavefronts), then ONE
// cp.async.bulk 32KB smem->gmem through the TMA engine.
// ---------------------------------------------------------------------------
__device__ __forceinline__ void edge_avg(uint4 ha, uint4 hd, float4& o0, float4& o1) {
    const __half2* pa = reinterpret_cast<const __half2*>(&ha);
    const __half2* pd = reinterpret_cast<const __half2*>(&hd);
    float2 a0 = __half22float2(pa[0]); float2 d0 = __half22float2(pd[0]);
    float2 a1 = __half22float2(pa[1]); float2 d1 = __half22float2(pd[1]);
    o0 = make_float4((a0.x + d0.x) * 0.5f, (a0.y + d0.y) * 0.5f,
                     (a1.x + d1.x) * 0.5f, (a1.y + d1.y) * 0.5f);
    float2 a2 = __half22float2(pa[2]); float2 d2 = __half22float2(pd[2]);
    float2 a3 = __half22float2(pa[3]); float2 d3 = __half22float2(pd[3]);
    o1 = make_float4((a2.x + d2.x) * 0.5f, (a2.y + d2.y) * 0.5f,
                     (a3.x + d3.x) * 0.5f, (a3.y + d3.y) * 0.5f);
}

#define EDGES_PER_BLK 128
__global__ void __launch_bounds__(256) k_edge(const void* __restrict__ edge_index,
                                              float* __restrict__ out) {
    __shared__ __align__(16) float sbuf[EDGES_PER_BLK * 64];   // 32KB

    const int tid = threadIdx.x;
    const int is64 = g_is64;
    const int c = tid & 7;          // 16B chunk within row
    const int r = tid >> 3;         // 0..31
    const int e_base = blockIdx.x * EDGES_PER_BLK;

    int s[4], d[4];
    #pragma unroll
    for (int i = 0; i < 4; i++) {
        int e = e_base + r + i * 32;
        s[i] = load_index(edge_index, e, is64);
        d[i] = load_index(edge_index, N_EDGES + e, is64);
    }

    const uint4* nb = reinterpret_cast<const uint4*>(g_nemb);
    uint4 zero = make_uint4(0u, 0u, 0u, 0u);
    uint4 ha[4], hd[4];
    // 8 independent L2 gathers in flight before any consumption
    #pragma unroll
    for (int i = 0; i < 4; i++) {
        ha[i] = ((unsigned)s[i] < N_NODES) ? __ldcg(nb + (size_t)s[i] * 8 + c) : zero;
        hd[i] = ((unsigned)d[i] < N_NODES) ? __ldcg(nb + (size_t)d[i] * 8 + c) : zero;
    }

    #pragma unroll
    for (int i = 0; i < 4; i++) {
        float4 o0, o1;
        edge_avg(ha[i], hd[i], o0, o1);
        float4* ps = reinterpret_cast<float4*>(&sbuf[(r + i * 32) * 64 + c * 8]);
        ps[0] = o0;
        ps[1] = o1;
    }
    __syncthreads();
    // order generic smem writes before the async-proxy bulk copy
    asm volatile("fence.proxy.async.shared::cta;" ::: "memory");

    if (tid == 0) {
        uint32_t saddr;
        asm("{ .reg .u64 t; cvta.to.shared.u64 t, %1; cvt.u32.u64 %0, t; }"
            : "=r"(saddr) : "l"(sbuf));
        float* gdst = out + (size_t)e_base * 64;
        asm volatile("cp.async.bulk.global.shared::cta.bulk_group [%0], [%1], %2;"
                     :: "l"(gdst), "r"(saddr), "n"(EDGES_PER_BLK * 64 * 4)
                     : "memory");
        asm volatile("cp.async.bulk.commit_group;" ::: "memory");
        asm volatile("cp.async.bulk.wait_group 0;" ::: "memory");
    }
}

// ---------------------------------------------------------------------------
// Inputs identified BY ELEMENT COUNT (robust to metadata ordering):
//   edge_attr  f32     [800000,64] -> 51,200,000
//   edge_index i32/i64 [2,800000]  ->  1,600,000
//   node_attr  f32     [50000,64]  ->  3,200,000
//   W          f32     [64,64]     ->      4,096
//   b          f32     [64]        ->         64
// Output: f32 [800000,64]
// ---------------------------------------------------------------------------
extern "C" void kernel_launch(void* const* d_in, const int* in_sizes, int n_in,
                              void* d_out, int out_size) {
    const float* edge_attr  = nullptr;
    const void*  edge_index = nullptr;
    const float* node_attr  = nullptr;
    const float* W          = nullptr;
    const float* b          = nullptr;

    int c32[4]; int n32 = 0;
    for (int i = 0; i < n_in; i++) {
        switch (in_sizes[i]) {
            case 51200000: edge_attr  = (const float*)d_in[i]; break;
            case 1600000:  edge_index = d_in[i];               break;
            case 3200000:  if (n32 < 4) c32[n32++] = i;        break;
            case 4096:     W          = (const float*)d_in[i]; break;
            case 64:       b          = (const float*)d_in[i]; break;
            default: break;
        }
    }
    if (n32 == 1) {
        node_attr = (const float*)d_in[c32[0]];
    } else if (n32 >= 2) {
        if (!edge_index) { edge_index = d_in[c32[0]]; node_attr = (const float*)d_in[c32[1]]; }
        else             { node_attr  = (const float*)d_in[c32[0]]; }
    }
    float* out = (float*)d_out;

    // zero scratch via memset graph nodes (no kernel, driver-optimized)
    void* agg_ptr = nullptr;
    void* cnt_ptr = nullptr;
    cudaGetSymbolAddress(&agg_ptr, g_agg);
    cudaGetSymbolAddress(&cnt_ptr, g_cnt);
    cudaMemsetAsync(agg_ptr, 0, (size_t)N_NODES * D * sizeof(float));
    cudaMemsetAsync(cnt_ptr, 0, (size_t)N_NODES * sizeof(float));

    k_detect<<<1, 256>>>((const int2*)edge_index);

    const int SCAT = (N_EDGES / 2) * 16;                  // 6.4M
    k_scatter<<<(SCAT + 255) / 256, 256>>>(edge_attr, edge_index);

    k_node<<<(N_NODES + 63) / 64, 256>>>(node_attr, W, b);

    k_edge<<<N_EDGES / EDGES_PER_BLK, 256>>>(edge_index, out);
}

// round 16
// speedup vs baseline: 1.2996x; 1.2996x over previous
#include <cuda_runtime.h>
#include <cuda_fp16.h>
#include <cuda_bf16.h>

#define N_NODES 50000
#define N_EDGES 800000
#define D 64

// Scratch (no allocations allowed): static device globals.
__device__ __align__(16) float  g_agg[N_NODES * D];   // scatter-sum of edge_attr
__device__ __align__(16) float  g_cnt[N_NODES];       // per-src edge counts
__device__ __align__(16) __half g_nemb[N_NODES * D];  // fp16 node embeddings (row = 128B)
__device__ int g_is64;                                // 1 = edge_index is int64

__device__ __forceinline__ int load_index(const void* ei, int pos, int is64) {
    if (is64) return (int)((const long long*)ei)[pos];
    return ((const int*)ei)[pos];
}

// ---------------------------------------------------------------------------
// k0: zero agg + cnt with float4 stores; block 0 also runs the int32/int64
// detection (int64 indices < 50000 -> all high words zero).
// (In-kernel zeroing is FASTER than cudaMemsetAsync graph nodes — measured
// R15: memset nodes cost ~+39us. Keep the kernel.)
// ---------------------------------------------------------------------------
__global__ void k_zero(const int2* __restrict__ ei) {
    if (blockIdx.x == 0) {
        int local = 0;
        for (int i = threadIdx.x; i < 4096; i += blockDim.x)
            local |= ei[i].y;
        __shared__ int any_hi;
        if (threadIdx.x == 0) any_hi = 0;
        __syncthreads();
        local |= __shfl_xor_sync(0xffffffffu, local, 16);
        local |= __shfl_xor_sync(0xffffffffu, local, 8);
        local |= __shfl_xor_sync(0xffffffffu, local, 4);
        local |= __shfl_xor_sync(0xffffffffu, local, 2);
        local |= __shfl_xor_sync(0xffffffffu, local, 1);
        if ((threadIdx.x & 31) == 0 && local) any_hi = 1;
        __syncthreads();
        if (threadIdx.x == 0) g_is64 = (any_hi == 0) ? 1 : 0;
    }
    int i = blockIdx.x * blockDim.x + threadIdx.x;
    const int AGG4 = (N_NODES * D) / 4;   // 800000
    const int CNT4 = N_NODES / 4;         // 12500
    float4 z = make_float4(0.f, 0.f, 0.f, 0.f);
    if (i < AGG4) {
        reinterpret_cast<float4*>(g_agg)[i] = z;
    } else if (i < AGG4 + CNT4) {
        reinterpret_cast<float4*>(g_cnt)[i - AGG4] = z;
    }
}

// ---------------------------------------------------------------------------
// k1: scatter-add edge_attr rows onto g_agg[src] with vector RED (v4.f32).
// 16 lanes per edge (dense row reads), TWO edges per thread (e, e+400000).
// edge_attr read once -> __ldcs streaming keeps g_agg L2-resident.
// ---------------------------------------------------------------------------
__global__ void k_scatter(const float* __restrict__ edge_attr,
                          const void* __restrict__ edge_index) {
    const int HALF = N_EDGES / 2;   // 400000
    int t = blockIdx.x * blockDim.x + threadIdx.x;
    if (t >= HALF * 16) return;
    int is64 = g_is64;
    int e0 = t >> 4;
    int c  = t & 15;
    int e1 = e0 + HALF;

    int s0 = load_index(edge_index, e0, is64);
    int s1 = load_index(edge_index, e1, is64);

    float4 v0 = __ldcs(reinterpret_cast<const float4*>(edge_attr) + (size_t)e0 * 16 + c);
    float4 v1 = __ldcs(reinterpret_cast<const float4*>(edge_attr) + (size_t)e1 * 16 + c);

    if ((unsigned)s0 < N_NODES) {
        float* p = &g_agg[s0 * D + c * 4];
        asm volatile("red.global.add.v4.f32 [%0], {%1,%2,%3,%4};"
                     :: "l"(p), "f"(v0.x), "f"(v0.y), "f"(v0.z), "f"(v0.w) : "memory");
        if (c == 0) atomicAdd(&g_cnt[s0], 1.0f);
    }
    if ((unsigned)s1 < N_NODES) {
        float* p = &g_agg[s1 * D + c * 4];
        asm volatile("red.global.add.v4.f32 [%0], {%1,%2,%3,%4};"
                     :: "l"(p), "f"(v1.x), "f"(v1.y), "f"(v1.z), "f"(v1.w) : "memory");
        if (c == 0) atomicAdd(&g_cnt[s1], 1.0f);
    }
}

// ---------------------------------------------------------------------------
// k2: nemb = sigmoid((node_attr + agg*0.5/max(cnt,1)) @ W^T + b), stored fp16.
// Register-tiled GEMM, 4x4 tile/thread, float4 LDS operand reads, stride 68.
// ---------------------------------------------------------------------------
#define S 68
__global__ void __launch_bounds__(256) k_node(const float* __restrict__ node_attr,
                                              const float* __restrict__ W,
                                              const float* __restrict__ b) {
    __shared__ float wt[64 * S];    // wt[k*S + j] = W[j*64 + k]
    __shared__ float xst[64 * S];   // xst[k*S + n] = x[node nb+n][k]
    __shared__ float bs[64];
    __shared__ float sinv[64];      // 0.5 / max(cnt, 1) per node

    const int tid = threadIdx.x;
    const int nb  = blockIdx.x * 64;

    if (tid < 64) {
        bs[tid] = b[tid];
        int n_g = nb + tid;
        float cnt = (n_g < N_NODES) ? g_cnt[n_g] : 1.0f;
        sinv[tid] = 0.5f / fmaxf(cnt, 1.0f);
    }
    #pragma unroll
    for (int i = tid; i < 64 * 64; i += 256) {
        int j = i >> 6;
        int k = i & 63;
        wt[k * S + j] = W[i];
    }
    __syncthreads();

    #pragma unroll
    for (int i = tid; i < 64 * 64; i += 256) {
        int n = i >> 6;
        int k = i & 63;
        int n_g = nb + n;
        float v = 0.0f;
        if (n_g < N_NODES) {
            v = node_attr[n_g * D + k] + g_agg[n_g * D + k] * sinv[n];
        }
        xst[k * S + n] = v;
    }
    __syncthreads();

    const int jg = tid & 15;
    const int ng = tid >> 4;
    const int j0 = jg * 4;
    const int n0 = ng * 4;

    float acc[4][4];
    #pragma unroll
    for (int a = 0; a < 4; a++)
        #pragma unroll
        for (int c = 0; c < 4; c++)
            acc[a][c] = bs[j0 + c];

    #pragma unroll 8
    for (int k = 0; k < 64; k++) {
        float4 xv = *reinterpret_cast<const float4*>(&xst[k * S + n0]);
        float4 wv = *reinterpret_cast<const float4*>(&wt[k * S + j0]);
        acc[0][0] = fmaf(xv.x, wv.x, acc[0][0]); acc[0][1] = fmaf(xv.x, wv.y, acc[0][1]);
        acc[0][2] = fmaf(xv.x, wv.z, acc[0][2]); acc[0][3] = fmaf(xv.x, wv.w, acc[0][3]);
        acc[1][0] = fmaf(xv.y, wv.x, acc[1][0]); acc[1][1] = fmaf(xv.y, wv.y, acc[1][1]);
        acc[1][2] = fmaf(xv.y, wv.z, acc[1][2]); acc[1][3] = fmaf(xv.y, wv.w, acc[1][3]);
        acc[2][0] = fmaf(xv.z, wv.x, acc[2][0]); acc[2][1] = fmaf(xv.z, wv.y, acc[2][1]);
        acc[2][2] = fmaf(xv.z, wv.z, acc[2][2]); acc[2][3] = fmaf(xv.z, wv.w, acc[2][3]);
        acc[3][0] = fmaf(xv.w, wv.x, acc[3][0]); acc[3][1] = fmaf(xv.w, wv.y, acc[3][1]);
        acc[3][2] = fmaf(xv.w, wv.z, acc[3][2]); acc[3][3] = fmaf(xv.w, wv.w, acc[3][3]);
    }

    #pragma unroll
    for (int a = 0; a < 4; a++) {
        int n_g = nb + n0 + a;
        if (n_g < N_NODES) {
            float s0 = 1.0f / (1.0f + __expf(-acc[a][0]));
            float s1 = 1.0f / (1.0f + __expf(-acc[a][1]));
            float s2 = 1.0f / (1.0f + __expf(-acc[a][2]));
            float s3 = 1.0f / (1.0f + __expf(-acc[a][3]));
            __half2 h0 = __floats2half2_rn(s0, s1);
            __half2 h1 = __floats2half2_rn(s2, s3);
            uint2 pk;
            pk.x = *reinterpret_cast<unsigned int*>(&h0);
            pk.y = *reinterpret_cast<unsigned int*>(&h1);
            *reinterpret_cast<uint2*>(&g_nemb[n_g * D + j0]) = pk;
        }
    }
}
#undef S

// ---------------------------------------------------------------------------
// k3: edge output: out[e] = (nemb[src] + nemb[dst]) * 0.5
// 8 lanes per edge (dense rows), FOUR edges per thread (stride 200000):
// 8 independent L2 gathers in flight (MLP=8), index loads amortized.
// Stores keep R11-13's proven dense STG.128 layout with __stcs streaming.
// ---------------------------------------------------------------------------
__device__ __forceinline__ void edge_avg(uint4 ha, uint4 hd, float4& o0, float4& o1) {
    const __half2* pa = reinterpret_cast<const __half2*>(&ha);
    const __half2* pd = reinterpret_cast<const __half2*>(&hd);
    float2 a0 = __half22float2(pa[0]); float2 d0 = __half22float2(pd[0]);
    float2 a1 = __half22float2(pa[1]); float2 d1 = __half22float2(pd[1]);
    o0 = make_float4((a0.x + d0.x) * 0.5f, (a0.y + d0.y) * 0.5f,
                     (a1.x + d1.x) * 0.5f, (a1.y + d1.y) * 0.5f);
    float2 a2 = __half22float2(pa[2]); float2 d2 = __half22float2(pd[2]);
    float2 a3 = __half22float2(pa[3]); float2 d3 = __half22float2(pd[3]);
    o1 = make_float4((a2.x + d2.x) * 0.5f, (a2.y + d2.y) * 0.5f,
                     (a3.x + d3.x) * 0.5f, (a3.y + d3.y) * 0.5f);
}

__global__ void __launch_bounds__(256) k_edge(const void* __restrict__ edge_index,
                                              float* __restrict__ out) {
    const int QUARTER = N_EDGES / 4;   // 200000
    int t = blockIdx.x * blockDim.x + threadIdx.x;
    if (t >= QUARTER * 8) return;
    const int is64 = g_is64;
    const int eb = t >> 3;
    const int c  = t & 7;

    int s[4], d[4];
    #pragma unroll
    for (int i = 0; i < 4; i++) {
        int e = eb + i * QUARTER;
        s[i] = load_index(edge_index, e, is64);
        d[i] = load_index(edge_index, N_EDGES + e, is64);
    }

    const uint4* nb = reinterpret_cast<const uint4*>(g_nemb);
    uint4 zero = make_uint4(0u, 0u, 0u, 0u);
    uint4 ha[4], hd[4];
    // 8 independent L2 gathers in flight before any consumption
    #pragma unroll
    for (int i = 0; i < 4; i++) {
        ha[i] = ((unsigned)s[i] < N_NODES) ? __ldcg(nb + (size_t)s[i] * 8 + c) : zero;
        hd[i] = ((unsigned)d[i] < N_NODES) ? __ldcg(nb + (size_t)d[i] * 8 + c) : zero;
    }

    #pragma unroll
    for (int i = 0; i < 4; i++) {
        float4 o0, o1;
        edge_avg(ha[i], hd[i], o0, o1);
        float4* po = reinterpret_cast<float4*>(out)
                     + (size_t)(eb + i * QUARTER) * 16 + c * 2;
        __stcs(po + 0, o0);
        __stcs(po + 1, o1);
    }
}

// ---------------------------------------------------------------------------
// Inputs identified BY ELEMENT COUNT (robust to metadata ordering):
//   edge_attr  f32     [800000,64] -> 51,200,000
//   edge_index i32/i64 [2,800000]  ->  1,600,000
//   node_attr  f32     [50000,64]  ->  3,200,000
//   W          f32     [64,64]     ->      4,096
//   b          f32     [64]        ->         64
// Output: f32 [800000,64]
// ---------------------------------------------------------------------------
extern "C" void kernel_launch(void* const* d_in, const int* in_sizes, int n_in,
                              void* d_out, int out_size) {
    const float* edge_attr  = nullptr;
    const void*  edge_index = nullptr;
    const float* node_attr  = nullptr;
    const float* W          = nullptr;
    const float* b          = nullptr;

    int c32[4]; int n32 = 0;
    for (int i = 0; i < n_in; i++) {
        switch (in_sizes[i]) {
            case 51200000: edge_attr  = (const float*)d_in[i]; break;
            case 1600000:  edge_index = d_in[i];               break;
            case 3200000:  if (n32 < 4) c32[n32++] = i;        break;
            case 4096:     W          = (const float*)d_in[i]; break;
            case 64:       b          = (const float*)d_in[i]; break;
            default: break;
        }
    }
    if (n32 == 1) {
        node_attr = (const float*)d_in[c32[0]];
    } else if (n32 >= 2) {
        if (!edge_index) { edge_index = d_in[c32[0]]; node_attr = (const float*)d_in[c32[1]]; }
        else             { node_attr  = (const float*)d_in[c32[0]]; }
    }
    float* out = (float*)d_out;

    const int ZERO4 = (N_NODES * D) / 4 + N_NODES / 4;   // 812500
    k_zero<<<(ZERO4 + 255) / 256, 256>>>((const int2*)edge_index);

    const int SCAT = (N_EDGES / 2) * 16;                  // 6.4M
    k_scatter<<<(SCAT + 255) / 256, 256>>>(edge_attr, edge_index);

    k_node<<<(N_NODES + 63) / 64, 256>>>(node_attr, W, b);

    const int EDG = (N_EDGES / 4) * 8;                    // 1.6M
    k_edge<<<(EDG + 255) / 256, 256>>>(edge_index, out);
}

// round 17
// speedup vs baseline: 1.4597x; 1.1232x over previous
#include <cuda_runtime.h>
#include <cuda_fp16.h>
#include <cuda_bf16.h>

#define N_NODES 50000
#define N_EDGES 800000
#define D 64

// Scratch (no allocations allowed): static device globals.
__device__ __align__(16) float  g_agg[N_NODES * D];   // scatter-sum of edge_attr
__device__ __align__(16) float  g_cnt[N_NODES];       // per-src edge counts
__device__ __align__(16) __half g_nemb[N_NODES * D];  // fp16 node embeddings (row = 128B)
__device__ int g_is64;                                // 1 = edge_index is int64

__device__ __forceinline__ int load_index(const void* ei, int pos, int is64) {
    if (is64) return (int)((const long long*)ei)[pos];
    return ((const int*)ei)[pos];
}

// ---------------------------------------------------------------------------
// k0: zero agg + cnt with float4 stores; block 0 also runs the int32/int64
// detection (int64 indices < 50000 -> all high words zero).
// (In-kernel zeroing beats cudaMemsetAsync graph nodes — measured R15.)
// ---------------------------------------------------------------------------
__global__ void k_zero(const int2* __restrict__ ei) {
    if (blockIdx.x == 0) {
        int local = 0;
        for (int i = threadIdx.x; i < 4096; i += blockDim.x)
            local |= ei[i].y;
        __shared__ int any_hi;
        if (threadIdx.x == 0) any_hi = 0;
        __syncthreads();
        local |= __shfl_xor_sync(0xffffffffu, local, 16);
        local |= __shfl_xor_sync(0xffffffffu, local, 8);
        local |= __shfl_xor_sync(0xffffffffu, local, 4);
        local |= __shfl_xor_sync(0xffffffffu, local, 2);
        local |= __shfl_xor_sync(0xffffffffu, local, 1);
        if ((threadIdx.x & 31) == 0 && local) any_hi = 1;
        __syncthreads();
        if (threadIdx.x == 0) g_is64 = (any_hi == 0) ? 1 : 0;
    }
    int i = blockIdx.x * blockDim.x + threadIdx.x;
    const int AGG4 = (N_NODES * D) / 4;   // 800000
    const int CNT4 = N_NODES / 4;         // 12500
    float4 z = make_float4(0.f, 0.f, 0.f, 0.f);
    if (i < AGG4) {
        reinterpret_cast<float4*>(g_agg)[i] = z;
    } else if (i < AGG4 + CNT4) {
        reinterpret_cast<float4*>(g_cnt)[i - AGG4] = z;
    }
}

// ---------------------------------------------------------------------------
// k1: scatter-add edge_attr rows onto g_agg[src] with vector RED (v4.f32).
// 16 lanes per edge (dense row reads), TWO edges per thread (e, e+400000).
// edge_attr read once -> __ldcs streaming keeps g_agg L2-resident.
// ---------------------------------------------------------------------------
__global__ void k_scatter(const float* __restrict__ edge_attr,
                          const void* __restrict__ edge_index) {
    const int HALF = N_EDGES / 2;   // 400000
    int t = blockIdx.x * blockDim.x + threadIdx.x;
    if (t >= HALF * 16) return;
    int is64 = g_is64;
    int e0 = t >> 4;
    int c  = t & 15;
    int e1 = e0 + HALF;

    int s0 = load_index(edge_index, e0, is64);
    int s1 = load_index(edge_index, e1, is64);

    float4 v0 = __ldcs(reinterpret_cast<const float4*>(edge_attr) + (size_t)e0 * 16 + c);
    float4 v1 = __ldcs(reinterpret_cast<const float4*>(edge_attr) + (size_t)e1 * 16 + c);

    if ((unsigned)s0 < N_NODES) {
        float* p = &g_agg[s0 * D + c * 4];
        asm volatile("red.global.add.v4.f32 [%0], {%1,%2,%3,%4};"
                     :: "l"(p), "f"(v0.x), "f"(v0.y), "f"(v0.z), "f"(v0.w) : "memory");
        if (c == 0) atomicAdd(&g_cnt[s0], 1.0f);
    }
    if ((unsigned)s1 < N_NODES) {
        float* p = &g_agg[s1 * D + c * 4];
        asm volatile("red.global.add.v4.f32 [%0], {%1,%2,%3,%4};"
                     :: "l"(p), "f"(v1.x), "f"(v1.y), "f"(v1.z), "f"(v1.w) : "memory");
        if (c == 0) atomicAdd(&g_cnt[s1], 1.0f);
    }
}

// ---------------------------------------------------------------------------
// k2: nemb = sigmoid((node_attr + agg*0.5/max(cnt,1)) @ W^T + b), stored fp16.
// Register-tiled GEMM, 4x4 tile/thread, float4 LDS operand reads, stride 68.
// ---------------------------------------------------------------------------
#define S 68
__global__ void __launch_bounds__(256) k_node(const float* __restrict__ node_attr,
                                              const float* __restrict__ W,
                                              const float* __restrict__ b) {
    __shared__ float wt[64 * S];    // wt[k*S + j] = W[j*64 + k]
    __shared__ float xst[64 * S];   // xst[k*S + n] = x[node nb+n][k]
    __shared__ float bs[64];
    __shared__ float sinv[64];      // 0.5 / max(cnt, 1) per node

    const int tid = threadIdx.x;
    const int nb  = blockIdx.x * 64;

    if (tid < 64) {
        bs[tid] = b[tid];
        int n_g = nb + tid;
        float cnt = (n_g < N_NODES) ? g_cnt[n_g] : 1.0f;
        sinv[tid] = 0.5f / fmaxf(cnt, 1.0f);
    }
    #pragma unroll
    for (int i = tid; i < 64 * 64; i += 256) {
        int j = i >> 6;
        int k = i & 63;
        wt[k * S + j] = W[i];
    }
    __syncthreads();

    #pragma unroll
    for (int i = tid; i < 64 * 64; i += 256) {
        int n = i >> 6;
        int k = i & 63;
        int n_g = nb + n;
        float v = 0.0f;
        if (n_g < N_NODES) {
            v = node_attr[n_g * D + k] + g_agg[n_g * D + k] * sinv[n];
        }
        xst[k * S + n] = v;
    }
    __syncthreads();

    const int jg = tid & 15;
    const int ng = tid >> 4;
    const int j0 = jg * 4;
    const int n0 = ng * 4;

    float acc[4][4];
    #pragma unroll
    for (int a = 0; a < 4; a++)
        #pragma unroll
        for (int c = 0; c < 4; c++)
            acc[a][c] = bs[j0 + c];

    #pragma unroll 8
    for (int k = 0; k < 64; k++) {
        float4 xv = *reinterpret_cast<const float4*>(&xst[k * S + n0]);
        float4 wv = *reinterpret_cast<const float4*>(&wt[k * S + j0]);
        acc[0][0] = fmaf(xv.x, wv.x, acc[0][0]); acc[0][1] = fmaf(xv.x, wv.y, acc[0][1]);
        acc[0][2] = fmaf(xv.x, wv.z, acc[0][2]); acc[0][3] = fmaf(xv.x, wv.w, acc[0][3]);
        acc[1][0] = fmaf(xv.y, wv.x, acc[1][0]); acc[1][1] = fmaf(xv.y, wv.y, acc[1][1]);
        acc[1][2] = fmaf(xv.y, wv.z, acc[1][2]); acc[1][3] = fmaf(xv.y, wv.w, acc[1][3]);
        acc[2][0] = fmaf(xv.z, wv.x, acc[2][0]); acc[2][1] = fmaf(xv.z, wv.y, acc[2][1]);
        acc[2][2] = fmaf(xv.z, wv.z, acc[2][2]); acc[2][3] = fmaf(xv.z, wv.w, acc[2][3]);
        acc[3][0] = fmaf(xv.w, wv.x, acc[3][0]); acc[3][1] = fmaf(xv.w, wv.y, acc[3][1]);
        acc[3][2] = fmaf(xv.w, wv.z, acc[3][2]); acc[3][3] = fmaf(xv.w, wv.w, acc[3][3]);
    }

    #pragma unroll
    for (int a = 0; a < 4; a++) {
        int n_g = nb + n0 + a;
        if (n_g < N_NODES) {
            float s0 = 1.0f / (1.0f + __expf(-acc[a][0]));
            float s1 = 1.0f / (1.0f + __expf(-acc[a][1]));
            float s2 = 1.0f / (1.0f + __expf(-acc[a][2]));
            float s3 = 1.0f / (1.0f + __expf(-acc[a][3]));
            __half2 h0 = __floats2half2_rn(s0, s1);
            __half2 h1 = __floats2half2_rn(s2, s3);
            uint2 pk;
            pk.x = *reinterpret_cast<unsigned int*>(&h0);
            pk.y = *reinterpret_cast<unsigned int*>(&h1);
            *reinterpret_cast<uint2*>(&g_nemb[n_g * D + j0]) = pk;
        }
    }
}
#undef S

// ---------------------------------------------------------------------------
// k3: edge output: out[e] = (nemb[src] + nemb[dst]) * 0.5
// FIXED STORE LAYOUT: 16 lanes per edge; lane c gathers 8B (4 fp16, features
// 4c..4c+3) from each node row via LDG.64 (16 lanes = dense 128B row) and
// stores ONE float4 at out + e*16 + c. Every STG.128 warp-instruction now
// covers 512B fully contiguous (full 32B sectors only) — the previous layout
// interleaved two STGs at 32B stride, splitting every output sector across
// two instructions (partial-sector DRAM writes -> RMW).
// TWO edges per thread (e, e+400000) for gather MLP=4.
// ---------------------------------------------------------------------------
__device__ __forceinline__ float4 avg8(uint2 ha, uint2 hd) {
    const __half2* pa = reinterpret_cast<const __half2*>(&ha);
    const __half2* pd = reinterpret_cast<const __half2*>(&hd);
    float2 a0 = __half22float2(pa[0]); float2 d0 = __half22float2(pd[0]);
    float2 a1 = __half22float2(pa[1]); float2 d1 = __half22float2(pd[1]);
    return make_float4((a0.x + d0.x) * 0.5f, (a0.y + d0.y) * 0.5f,
                       (a1.x + d1.x) * 0.5f, (a1.y + d1.y) * 0.5f);
}

__global__ void __launch_bounds__(256) k_edge(const void* __restrict__ edge_index,
                                              float* __restrict__ out) {
    const int HALF = N_EDGES / 2;   // 400000
    int t = blockIdx.x * blockDim.x + threadIdx.x;
    if (t >= HALF * 16) return;
    const int is64 = g_is64;
    const int e0 = t >> 4;
    const int c  = t & 15;
    const int e1 = e0 + HALF;

    int s0 = load_index(edge_index, e0, is64);
    int d0 = load_index(edge_index, N_EDGES + e0, is64);
    int s1 = load_index(edge_index, e1, is64);
    int d1 = load_index(edge_index, N_EDGES + e1, is64);

    const uint2* nb = reinterpret_cast<const uint2*>(g_nemb);  // row = 16 uint2
    uint2 zero = make_uint2(0u, 0u);
    // 4 independent L2 gathers in flight before any consumption
    uint2 ha0 = ((unsigned)s0 < N_NODES) ? __ldcg(nb + (size_t)s0 * 16 + c) : zero;
    uint2 hd0 = ((unsigned)d0 < N_NODES) ? __ldcg(nb + (size_t)d0 * 16 + c) : zero;
    uint2 ha1 = ((unsigned)s1 < N_NODES) ? __ldcg(nb + (size_t)s1 * 16 + c) : zero;
    uint2 hd1 = ((unsigned)d1 < N_NODES) ? __ldcg(nb + (size_t)d1 * 16 + c) : zero;

    // dense full-sector stores: lane c -> float4 index c of the 256B row
    __stcs(reinterpret_cast<float4*>(out) + (size_t)e0 * 16 + c, avg8(ha0, hd0));
    __stcs(reinterpret_cast<float4*>(out) + (size_t)e1 * 16 + c, avg8(ha1, hd1));
}

// ---------------------------------------------------------------------------
// Inputs identified BY ELEMENT COUNT (robust to metadata ordering):
//   edge_attr  f32     [800000,64] -> 51,200,000
//   edge_index i32/i64 [2,800000]  ->  1,600,000
//   node_attr  f32     [50000,64]  ->  3,200,000
//   W          f32     [64,64]     ->      4,096
//   b          f32     [64]        ->         64
// Output: f32 [800000,64]
// ---------------------------------------------------------------------------
extern "C" void kernel_launch(void* const* d_in, const int* in_sizes, int n_in,
                              void* d_out, int out_size) {
    const float* edge_attr  = nullptr;
    const void*  edge_index = nullptr;
    const float* node_attr  = nullptr;
    const float* W          = nullptr;
    const float* b          = nullptr;

    int c32[4]; int n32 = 0;
    for (int i = 0; i < n_in; i++) {
        switch (in_sizes[i]) {
            case 51200000: edge_attr  = (const float*)d_in[i]; break;
            case 1600000:  edge_index = d_in[i];               break;
            case 3200000:  if (n32 < 4) c32[n32++] = i;        break;
            case 4096:     W          = (const float*)d_in[i]; break;
            case 64:       b          = (const float*)d_in[i]; break;
            default: break;
        }
    }
    if (n32 == 1) {
        node_attr = (const float*)d_in[c32[0]];
    } else if (n32 >= 2) {
        if (!edge_index) { edge_index = d_in[c32[0]]; node_attr = (const float*)d_in[c32[1]]; }
        else             { node_attr  = (const float*)d_in[c32[0]]; }
    }
    float* out = (float*)d_out;

    const int ZERO4 = (N_NODES * D) / 4 + N_NODES / 4;   // 812500
    k_zero<<<(ZERO4 + 255) / 256, 256>>>((const int2*)edge_index);

    const int SCAT = (N_EDGES / 2) * 16;                  // 6.4M
    k_scatter<<<(SCAT + 255) / 256, 256>>>(edge_attr, edge_index);

    k_node<<<(N_NODES + 63) / 64, 256>>>(node_attr, W, b);

    const int EDG = (N_EDGES / 2) * 16;                   // 6.4M
    k_edge<<<(EDG + 255) / 256, 256>>>(edge_index, out);
}